// round 16
// baseline (speedup 1.0000x reference)
#include <cuda_runtime.h>
#include <cuda_bf16.h>
#include <cstdint>
#include <math.h>

// ---------------------------------------------------------------------------
// HATBlock — Round 16: MLP1+MLP2 fused into one kernel (hidden stays in smem;
// 604 MB DRAM round-trip removed).  R15 fused QKV+attention kept.
// B=4, C=256, H=W=192, WS=8, NH=8, HD=32
// ---------------------------------------------------------------------------

#define BATCH 4
#define DIM   256
#define HH    192
#define WW_   192
#define NWH   24
#define NWIN  (BATCH*NWH*NWH)   // 2304
#define NTOK  (NWIN*64)         // 147456
#define NH    8
#define TOK_PER_B (HH*WW_)      // 36864

typedef unsigned long long u64;
typedef unsigned int u32;

// -------------------- scratch (device globals; no runtime alloc) -----------
__device__ float g_wins[(size_t)NTOK*256];   // wins / y (fp32)
__device__ float g_h   [(size_t)NTOK*256];   // attn-out bf16 alias / final fp32
__device__ float g_part[1024];
__device__ float g_gate[BATCH*256];
__device__ float g_wb  [786432/2];           // bf16 weights

__device__ __forceinline__ float gelu_exact(float x) {
    return 0.5f * x * (1.0f + erff(x * 0.70710678118654752f));
}

__device__ __forceinline__ void cp_async16(void* smem, const void* gmem) {
    unsigned s = (unsigned)__cvta_generic_to_shared(smem);
    asm volatile("cp.async.ca.shared.global [%0], [%1], 16;" :: "r"(s), "l"(gmem));
}
__device__ __forceinline__ void cp_commit() { asm volatile("cp.async.commit_group;"); }
__device__ __forceinline__ void cp_wait0()  { asm volatile("cp.async.wait_group 0;" ::: "memory"); }
__device__ __forceinline__ void cp_wait1()  { asm volatile("cp.async.wait_group 1;" ::: "memory"); }
__device__ __forceinline__ void cp_wait2()  { asm volatile("cp.async.wait_group 2;" ::: "memory"); }
__device__ __forceinline__ void cp_wait3()  { asm volatile("cp.async.wait_group 3;" ::: "memory"); }

__device__ __forceinline__ void mma_bf16(float* c, const u32* a, const u32* b) {
    asm volatile(
        "mma.sync.aligned.m16n8k16.row.col.f32.bf16.bf16.f32 "
        "{%0,%1,%2,%3},{%4,%5,%6,%7},{%8,%9},{%0,%1,%2,%3};"
        : "+f"(c[0]), "+f"(c[1]), "+f"(c[2]), "+f"(c[3])
        : "r"(a[0]), "r"(a[1]), "r"(a[2]), "r"(a[3]), "r"(b[0]), "r"(b[1]));
}

__device__ __forceinline__ void ldsm4(u32& r0, u32& r1, u32& r2, u32& r3, u32 addr) {
    asm volatile("ldmatrix.sync.aligned.m8n8.x4.shared.b16 {%0,%1,%2,%3}, [%4];"
                 : "=r"(r0), "=r"(r1), "=r"(r2), "=r"(r3) : "r"(addr));
}

__device__ __forceinline__ u32 packbf(float a, float b) {
    __nv_bfloat162 t = __float22bfloat162_rn(make_float2(a, b));
    return *(u32*)&t;
}

// -------------------- weight prep: fp32 [K,N] -> bf16 [N,K] (+row remap) ---
__device__ __forceinline__ void wprep_body(const float* in, __nv_bfloat16* out,
                                           int K, int N, int n0, int k0, int outRow0) {
    __shared__ float tile[32][33];
    for (int r = threadIdx.y; r < 32; r += 8)
        tile[r][threadIdx.x] = in[(size_t)(k0 + r) * N + n0 + threadIdx.x];
    __syncthreads();
    for (int r = threadIdx.y; r < 32; r += 8)
        out[(size_t)(outRow0 + r) * K + k0 + threadIdx.x] = __float2bfloat16_rn(tile[threadIdx.x][r]);
}

// all four weights in one launch (768 blocks)
__global__ void k_wprep4(const float* __restrict__ qkv_w, __nv_bfloat16* __restrict__ qkvW,
                         const float* __restrict__ w1,    __nv_bfloat16* __restrict__ w1W,
                         const float* __restrict__ proj,  __nv_bfloat16* __restrict__ projW,
                         const float* __restrict__ w2,    __nv_bfloat16* __restrict__ w2W) {
    int blk = blockIdx.x;
    if (blk < 192) {                       // qkv: N=768,K=256, head-pack remap
        int n0 = (blk % 24) * 32, k0 = (blk / 24) * 32;
        int part = n0 >> 8, h = (n0 & 255) >> 5;
        wprep_body(qkv_w, qkvW, 256, 768, n0, k0, h*96 + part*32);
    } else if (blk < 448) {                // w1: N=1024,K=256
        blk -= 192;
        int n0 = (blk % 32) * 32, k0 = (blk / 32) * 32;
        wprep_body(w1, w1W, 256, 1024, n0, k0, n0);
    } else if (blk < 512) {                // proj: N=256,K=256
        blk -= 448;
        int n0 = (blk % 8) * 32, k0 = (blk / 8) * 32;
        wprep_body(proj, projW, 256, 256, n0, k0, n0);
    } else {                               // w2: N=256,K=1024
        blk -= 512;
        int n0 = (blk % 8) * 32, k0 = (blk / 8) * 32;
        wprep_body(w2, w2W, 1024, 256, n0, k0, n0);
    }
}

// -------------------- window partition (+ zero pooled sums) ----------------
__global__ void k_winpart(const float* __restrict__ x, float* __restrict__ wins,
                          float* __restrict__ part) {
    int w0 = blockIdx.x * 32, hh = blockIdx.y;
    int b = blockIdx.z >> 3, c0 = (blockIdx.z & 7) * 32;
    if (blockIdx.x == 0 && blockIdx.y == 0 && blockIdx.z == 0) {
        int t = threadIdx.y * 32 + threadIdx.x;
#pragma unroll
        for (int i = 0; i < 4; i++) part[t + 256*i] = 0.f;
    }
    __shared__ float tile[32][33];
    for (int cc = threadIdx.y; cc < 32; cc += 8)
        tile[cc][threadIdx.x] =
            x[(((size_t)b*256 + c0 + cc)*HH + hh)*WW_ + w0 + threadIdx.x];
    __syncthreads();
    int hw = hh >> 3, i = hh & 7;
    for (int wi = threadIdx.y; wi < 32; wi += 8) {
        int w = w0 + wi, ww = w >> 3, j = w & 7;
        size_t t = (((size_t)b*NWH + hw)*NWH + ww)*64 + i*8 + j;
        wins[t*256 + c0 + threadIdx.x] = tile[threadIdx.x][wi];
    }
}

// -------------------- window reverse: z[t,c] -> out[B,C,H,W] ---------------
__global__ void k_winrev(const float* __restrict__ z, float* __restrict__ out) {
    int w0 = blockIdx.x * 32, hh = blockIdx.y;
    int b = blockIdx.z >> 3, c0 = (blockIdx.z & 7) * 32;
    __shared__ float tile[32][33];
    int hw = hh >> 3, i = hh & 7;
    for (int wi = threadIdx.y; wi < 32; wi += 8) {
        int w = w0 + wi, ww = w >> 3, j = w & 7;
        size_t t = (((size_t)b*NWH + hw)*NWH + ww)*64 + i*8 + j;
        tile[wi][threadIdx.x] = z[t*256 + c0 + threadIdx.x];
    }
    __syncthreads();
    for (int cc = threadIdx.y; cc < 32; cc += 8)
        out[(((size_t)b*256 + c0 + cc)*HH + hh)*WW_ + w0 + threadIdx.x] =
            tile[threadIdx.x][cc];
}

// ============================================================================
// Fused QKV GEMM + window attention (unchanged from R15).
// ============================================================================
#define F_AB_STR 264
#define F_QK_STR 72
#define F_VT_STR 136
#define FS_QK   67584
#define FS_VT   86016
#define FS_RING 94720
#define FS_RSTG 7680
#define FS_PB   110080
#define FS_SB   110464
#define FS_SMEM 111368

__global__ void __launch_bounds__(256, 2)
k_fused_qkv_attn(const float* __restrict__ Ain,
                 const float* __restrict__ lng, const float* __restrict__ lnb,
                 const __nv_bfloat16* __restrict__ Wt,   // packed [8][96][256]
                 const float* __restrict__ qkv_b,
                 const float* __restrict__ rel_bias,
                 __nv_bfloat16* __restrict__ hb)
{
    extern __shared__ char smem[];
    __nv_bfloat16* Ab  = (__nv_bfloat16*)smem;
    __nv_bfloat16* qk  = (__nv_bfloat16*)(smem + FS_QK);
    __nv_bfloat16* vT  = (__nv_bfloat16*)(smem + FS_VT);
    float* pb  = (float*)(smem + FS_PB);
    float* sbt = (float*)(smem + FS_SB);
    const u32 sbase = (u32)__cvta_generic_to_shared(smem);

    const int tid = threadIdx.x, lane = tid & 31, wid = tid >> 5;
    const int g = lane >> 2, tig = lane & 3;
    const int m0 = blockIdx.x * 128;

    const int a_dr = (lane & 7) | (((lane >> 3) & 1) << 3);
    const int a_dk = (lane >> 4) << 3;
    const int quad = lane >> 3;
    const int b_dc = (lane & 7) + ((quad & 2) ? 8 : 0);
    const int b_dk = (quad & 1) << 3;

    const int wm = wid & 3;
    const int wn = wid >> 2;
    const int wi = wid >> 2;
    const int qt = wid & 3;

    auto fillW = [&](int hc) {
        __nv_bfloat16* Bs = (__nv_bfloat16*)(smem + FS_RING + (hc & 1) * FS_RSTG);
        const __nv_bfloat16* Wg = Wt + (size_t)(hc >> 3) * 96 * 256 + (hc & 7) * 32;
#pragma unroll
        for (int i = 0; i < 2; i++) {
            int idx = tid + 256*i;
            if (idx < 384) {
                int row = idx >> 2, seg = idx & 3;
                cp_async16(Bs + row*40 + seg*8, Wg + (size_t)row*256 + seg*8);
            }
        }
        cp_commit();
    };
    fillW(0); fillW(1);

    {
        const float* Ag = Ain + (size_t)m0 * 256;
        float lg[8], lb[8];
#pragma unroll
        for (int j = 0; j < 8; j++) {
            int c = lane*8 + j;
            lg[j] = lng[c]; lb[j] = lnb[c];
        }
#pragma unroll 1
        for (int i = 0; i < 16; i++) {
            int r = wid*16 + i;
            const float4* rp = (const float4*)(Ag + (size_t)r * 256 + lane*8);
            float4 va = rp[0], vb = rp[1];
            float v[8] = {va.x, va.y, va.z, va.w, vb.x, vb.y, vb.z, vb.w};
            float s = 0.f, s2 = 0.f;
#pragma unroll
            for (int j = 0; j < 8; j++) { s += v[j]; s2 += v[j]*v[j]; }
#pragma unroll
            for (int o = 16; o; o >>= 1) {
                s  += __shfl_xor_sync(0xffffffffu, s,  o);
                s2 += __shfl_xor_sync(0xffffffffu, s2, o);
            }
            float mean = s * (1.f/256.f);
            float var  = s2 * (1.f/256.f) - mean*mean;
            float inv  = rsqrtf(var + 1e-5f);
#pragma unroll
            for (int k = 0; k < 4; k++) {
                float n0 = (v[2*k  ]-mean)*inv*lg[2*k  ] + lb[2*k  ];
                float n1 = (v[2*k+1]-mean)*inv*lg[2*k+1] + lb[2*k+1];
                *(u32*)&Ab[r*F_AB_STR + lane*8 + 2*k] = packbf(n0, n1);
            }
        }
    }

#pragma unroll 1
    for (int h = 0; h < 8; h++) {
        float acc[2][6][4];
#pragma unroll
        for (int i = 0; i < 2; i++)
#pragma unroll
            for (int j = 0; j < 6; j++)
#pragma unroll
                for (int q = 0; q < 4; q++) acc[i][j][q] = 0.f;

#pragma unroll 1
        for (int ck = 0; ck < 8; ck++) {
            const int hc = h*8 + ck;
            if (hc == 63) cp_wait0(); else cp_wait1();
            __syncthreads();
            if (ck == 0) {
                for (int j = tid; j < 96; j += 256)
                    pb[j] = qkv_b[(j >> 5)*256 + h*32 + (j & 31)];
                for (int rr = tid; rr < 225; rr += 256)
                    sbt[rr] = rel_bias[rr*NH + h];
            }
            const u32 rb = sbase + FS_RING + (u32)(hc & 1) * FS_RSTG;
#pragma unroll
            for (int ks = 0; ks < 2; ks++) {
                const int kb = ck*32 + ks*16;
                u32 af[2][4], bf[6][2];
#pragma unroll
                for (int mt = 0; mt < 2; mt++) {
                    u32 aaddr = sbase + (u32)(((wm*32 + mt*16 + a_dr)*F_AB_STR + kb + a_dk) * 2);
                    ldsm4(af[mt][0], af[mt][1], af[mt][2], af[mt][3], aaddr);
                }
#pragma unroll
                for (int p = 0; p < 3; p++) {
                    u32 baddr = rb + (u32)(((wn*48 + p*16 + b_dc)*40 + ks*16 + b_dk) * 2);
                    ldsm4(bf[2*p][0], bf[2*p][1], bf[2*p+1][0], bf[2*p+1][1], baddr);
                }
#pragma unroll
                for (int mt = 0; mt < 2; mt++)
#pragma unroll
                    for (int nt = 0; nt < 6; nt++)
                        mma_bf16(acc[mt][nt], af[mt], bf[nt]);
            }
            __syncthreads();
            if (hc + 2 < 64) fillW(hc + 2);
        }

#pragma unroll
        for (int nt = 0; nt < 6; nt++) {
            int colj = wn*48 + nt*8 + 2*tig;
            float b0 = pb[colj], b1 = pb[colj + 1];
#pragma unroll
            for (int mt = 0; mt < 2; mt++) {
                int r0 = wm*32 + mt*16 + g, r1 = r0 + 8;
                float v00 = acc[mt][nt][0] + b0, v01 = acc[mt][nt][1] + b1;
                float v10 = acc[mt][nt][2] + b0, v11 = acc[mt][nt][3] + b1;
                if (colj < 64) {
                    *(u32*)&qk[r0*F_QK_STR + colj] = packbf(v00, v01);
                    *(u32*)&qk[r1*F_QK_STR + colj] = packbf(v10, v11);
                } else {
                    int c = colj - 64;
                    vT[c*F_VT_STR + r0]     = __float2bfloat16_rn(v00);
                    vT[(c+1)*F_VT_STR + r0] = __float2bfloat16_rn(v01);
                    vT[c*F_VT_STR + r1]     = __float2bfloat16_rn(v10);
                    vT[(c+1)*F_VT_STR + r1] = __float2bfloat16_rn(v11);
                }
            }
        }
        __syncthreads();

        u32 aQ[2][4];
#pragma unroll
        for (int ks = 0; ks < 2; ks++) {
            u32 aaddr = sbase + FS_QK +
                (u32)(((wi*64 + qt*16 + a_dr)*F_QK_STR + ks*16 + a_dk) * 2);
            ldsm4(aQ[ks][0], aQ[ks][1], aQ[ks][2], aQ[ks][3], aaddr);
        }

        float S[8][4];
#pragma unroll
        for (int j = 0; j < 8; j++)
#pragma unroll
            for (int q = 0; q < 4; q++) S[j][q] = 0.f;

#pragma unroll
        for (int ks = 0; ks < 2; ks++) {
            u32 bK[8][2];
#pragma unroll
            for (int p = 0; p < 4; p++) {
                u32 baddr = sbase + FS_QK +
                    (u32)(((wi*64 + p*16 + b_dc)*F_QK_STR + 32 + ks*16 + b_dk) * 2);
                ldsm4(bK[2*p][0], bK[2*p][1], bK[2*p+1][0], bK[2*p+1][1], baddr);
            }
#pragma unroll
            for (int nt = 0; nt < 8; nt++)
                mma_bf16(S[nt], aQ[ks], bK[nt]);
        }

#pragma unroll
        for (int nt = 0; nt < 8; nt++)
#pragma unroll
            for (int rr = 0; rr < 2; rr++)
#pragma unroll
                for (int e = 0; e < 2; e++) {
                    int di = qt*2 + rr - nt + 7;
                    int dj = g - (2*tig + e) + 7;
                    S[nt][rr*2+e] = S[nt][rr*2+e] * 0.17677669529663687f
                                  + sbt[di*15 + dj];
                }

        float lrow[2];
#pragma unroll
        for (int rr = 0; rr < 2; rr++) {
            float mx = -1e30f;
#pragma unroll
            for (int nt = 0; nt < 8; nt++) {
                mx = fmaxf(mx, S[nt][rr*2]);
                mx = fmaxf(mx, S[nt][rr*2+1]);
            }
            mx = fmaxf(mx, __shfl_xor_sync(0xffffffffu, mx, 1));
            mx = fmaxf(mx, __shfl_xor_sync(0xffffffffu, mx, 2));
            float sum = 0.f;
#pragma unroll
            for (int nt = 0; nt < 8; nt++) {
                float p0 = __expf(S[nt][rr*2]   - mx);
                float p1 = __expf(S[nt][rr*2+1] - mx);
                S[nt][rr*2] = p0; S[nt][rr*2+1] = p1;
                sum += p0 + p1;
            }
            sum += __shfl_xor_sync(0xffffffffu, sum, 1);
            sum += __shfl_xor_sync(0xffffffffu, sum, 2);
            lrow[rr] = sum;
        }

        float O[4][4];
#pragma unroll
        for (int j = 0; j < 4; j++)
#pragma unroll
            for (int q = 0; q < 4; q++) O[j][q] = 0.f;
#pragma unroll
        for (int ks2 = 0; ks2 < 4; ks2++) {
            u32 bV[4][2];
#pragma unroll
            for (int p = 0; p < 2; p++) {
                u32 vaddr = sbase + FS_VT +
                    (u32)(((p*16 + b_dc)*F_VT_STR + wi*64 + ks2*16 + b_dk) * 2);
                ldsm4(bV[2*p][0], bV[2*p][1], bV[2*p+1][0], bV[2*p+1][1], vaddr);
            }
            u32 pa[4];
            pa[0] = packbf(S[2*ks2  ][0], S[2*ks2  ][1]);
            pa[1] = packbf(S[2*ks2  ][2], S[2*ks2  ][3]);
            pa[2] = packbf(S[2*ks2+1][0], S[2*ks2+1][1]);
            pa[3] = packbf(S[2*ks2+1][2], S[2*ks2+1][3]);
#pragma unroll
            for (int nt2 = 0; nt2 < 4; nt2++)
                mma_bf16(O[nt2], pa, bV[nt2]);
        }

        float inv0 = 1.f / lrow[0], inv1 = 1.f / lrow[1];
        size_t rg = (size_t)m0 + wi*64 + qt*16 + g;
#pragma unroll
        for (int nt2 = 0; nt2 < 4; nt2++) {
            __nv_bfloat16* p0 = hb + rg*256 + h*32 + nt2*8 + 2*tig;
            *(u32*)(p0)         = packbf(O[nt2][0]*inv0, O[nt2][1]*inv0);
            *(u32*)(p0 + 8*256) = packbf(O[nt2][2]*inv1, O[nt2][3]*inv1);
        }
    }
}

// ============================================================================
// GEMM (proj): CTA 256x128, 8 warps, warp 64x64, K chunk 32, 4-stage B ring.
// ============================================================================
#define AB_STR 264
#define B_STR  40
#define SMA_BR   135168
#define SMA_SCOL 176128
#define SMA_SMEM 176640

__global__ void __launch_bounds__(256, 1)
k_gemm_smA(const __nv_bfloat16* __restrict__ Ain,
           const __nv_bfloat16* __restrict__ Wt,
           const float* __restrict__ bias,
           const float* __restrict__ R,
           float* __restrict__ Cf,
           int Nfull, float* __restrict__ pool)
{
    extern __shared__ char smem[];
    __nv_bfloat16* Ab = (__nv_bfloat16*)smem;
    char*  Bring = smem + SMA_BR;
    float* scol = (float*)(smem + SMA_SCOL);
    const u32 sbase = (u32)__cvta_generic_to_shared(smem);

    const int tid = threadIdx.x, lane = tid & 31, wid = tid >> 5;
    const int g = lane >> 2, tig = lane & 3;
    const int arow = (wid & 3) * 64;
    const int bcol = (wid >> 2) * 64;
    const int m0 = blockIdx.x * 256;
    const int b  = m0 / TOK_PER_B;

    const int a_dr = (lane & 7) | (((lane >> 3) & 1) << 3);
    const int a_dk = (lane >> 4) << 3;
    const int quad = lane >> 3;
    const int b_dc = (lane & 7) + ((quad & 2) ? 8 : 0);
    const int b_dk = (quad & 1) << 3;

    const __nv_bfloat16* Ag = Ain + (size_t)m0 * 256;
#pragma unroll
    for (int i = 0; i < 32; i++) {
        int idx = tid + 256*i;
        int r = idx >> 5, c8 = idx & 31;
        cp_async16(Ab + r*AB_STR + c8*8, Ag + (size_t)r*256 + c8*8);
    }
    cp_commit();

    const int NY = Nfull >> 7;
    const int KT = 8;
    const int TOT = NY * KT;

    auto fillB = [&](int c) {
        int ny2 = c >> 3, kt2 = c & 7, st = c & 3;
        __nv_bfloat16* Bs = (__nv_bfloat16*)(Bring + st*10240);
        const __nv_bfloat16* Wg = Wt + (size_t)(ny2*128) * 256 + kt2*32;
#pragma unroll
        for (int i = 0; i < 2; i++) {
            int idx = tid + 256*i;
            int row = idx >> 2, seg = idx & 3;
            cp_async16(Bs + row*B_STR + seg*8, Wg + (size_t)row*256 + seg*8);
        }
        cp_commit();
    };
    fillB(0); fillB(1); fillB(2);

    int ci = 0;
    for (int ny = 0; ny < NY; ny++) {
        float acc[4][8][4];
#pragma unroll
        for (int i = 0; i < 4; i++)
#pragma unroll
            for (int j = 0; j < 8; j++)
#pragma unroll
                for (int q = 0; q < 4; q++) acc[i][j][q] = 0.f;

        for (int kt = 0; kt < KT; kt++, ci++) {
            cp_wait2();
            __syncthreads();
            const u32 bsb = sbase + SMA_BR + (u32)(ci & 3)*10240;
#pragma unroll
            for (int ks = 0; ks < 2; ks++) {
                const int kb = kt*32 + ks*16;
                u32 af[4][4], bf[8][2];
#pragma unroll
                for (int mt = 0; mt < 4; mt++) {
                    u32 aaddr = sbase + (u32)(((arow + mt*16 + a_dr)*AB_STR + kb + a_dk) * 2);
                    ldsm4(af[mt][0], af[mt][1], af[mt][2], af[mt][3], aaddr);
                }
#pragma unroll
                for (int p = 0; p < 4; p++) {
                    u32 baddr = bsb + (u32)(((bcol + p*16 + b_dc)*B_STR + ks*16 + b_dk) * 2);
                    ldsm4(bf[2*p][0], bf[2*p][1], bf[2*p+1][0], bf[2*p+1][1], baddr);
                }
#pragma unroll
                for (int mt = 0; mt < 4; mt++)
#pragma unroll
                    for (int nt = 0; nt < 8; nt++)
                        mma_bf16(acc[mt][nt], af[mt], bf[nt]);
            }
            if (ci + 3 < TOT) fillB(ci + 3);
            else cp_commit();
        }

        const int ncol0 = ny * 128;
        float psum[8][2];
#pragma unroll
        for (int nt = 0; nt < 8; nt++) { psum[nt][0] = 0.f; psum[nt][1] = 0.f; }
#pragma unroll
        for (int nt = 0; nt < 8; nt++) {
            int colG = ncol0 + bcol + nt*8 + 2*tig;
            float b0 = bias[colG], b1 = bias[colG + 1];
#pragma unroll
            for (int mt = 0; mt < 4; mt++) {
                size_t r0 = (size_t)m0 + arow + mt*16 + g;
                size_t r1 = r0 + 8;
                float2 q0 = *(const float2*)(R + r0*Nfull + colG);
                float2 q1 = *(const float2*)(R + r1*Nfull + colG);
                float v00 = acc[mt][nt][0] + b0 + q0.x, v01 = acc[mt][nt][1] + b1 + q0.y;
                float v10 = acc[mt][nt][2] + b0 + q1.x, v11 = acc[mt][nt][3] + b1 + q1.y;
                *(float2*)(Cf + r0*Nfull + colG) = make_float2(v00, v01);
                *(float2*)(Cf + r1*Nfull + colG) = make_float2(v10, v11);
                psum[nt][0] += v00 + v10; psum[nt][1] += v01 + v11;
            }
        }
        __syncthreads();
        if (tid < 128) scol[tid] = 0.f;
        __syncthreads();
#pragma unroll
        for (int nt = 0; nt < 8; nt++) {
            int colL = bcol + nt*8 + 2*tig;
            atomicAdd(&scol[colL],     psum[nt][0]);
            atomicAdd(&scol[colL + 1], psum[nt][1]);
        }
        __syncthreads();
        if (tid < 128) atomicAdd(pool + b*256 + ncol0 + tid, scol[tid]);
        __syncthreads();
    }
}

// ============================================================================
// Fused MLP: gate+LN3 -> GEMM1(+gelu, hidden chunk in smem) -> GEMM2 accum.
// CTA = 128 tokens, 8 warps, 1 CTA/SM.  Hidden never touches gmem.
// smem: Ab 128x264 bf16 @0 (67,584); Hs 128x136 bf16 @67,584 (34,816);
//       W ring 5 x 20,480 @102,400; gate 256f @204,800.  Total 205,824.
// Chunk schedule per hidden block nh (8 of 128): 8 W1 K32-chunks, 4 W2 chunks.
// ============================================================================
#define FM_HS   67584
#define FM_RING 102400
#define FM_RSTG 20480
#define FM_GATE 204800
#define FM_SMEM 205824
#define FM_HS_STR 136

__global__ void __launch_bounds__(256, 1)
k_fused_mlp(const float* __restrict__ y,
            const float* __restrict__ gate,
            const float* __restrict__ n3g, const float* __restrict__ n3b,
            const __nv_bfloat16* __restrict__ W1t,   // [1024][256]
            const float* __restrict__ b1,
            const __nv_bfloat16* __restrict__ W2t,   // [256][1024]
            const float* __restrict__ b2,
            float* __restrict__ outT)                // fp32 [NTOK][256]
{
    extern __shared__ char smem[];
    __nv_bfloat16* Ab = (__nv_bfloat16*)smem;
    __nv_bfloat16* Hs = (__nv_bfloat16*)(smem + FM_HS);
    float* gsm = (float*)(smem + FM_GATE);
    const u32 sbase = (u32)__cvta_generic_to_shared(smem);

    const int tid = threadIdx.x, lane = tid & 31, wid = tid >> 5;
    const int g = lane >> 2, tig = lane & 3;
    const int wm = wid & 3;          // 32-row slice
    const int wn = wid >> 2;         // GEMM1: 64 cols; GEMM2: 128 cols
    const int m0 = blockIdx.x * 128;
    const int b  = m0 / TOK_PER_B;

    const int a_dr = (lane & 7) | (((lane >> 3) & 1) << 3);
    const int a_dk = (lane >> 4) << 3;
    const int quad = lane >> 3;
    const int b_dc = (lane & 7) + ((quad & 2) ? 8 : 0);
    const int b_dk = (quad & 1) << 3;

    auto fill = [&](int ci) {
        int nh2 = ci / 12, r = ci - nh2*12, st = ci % 5;
        __nv_bfloat16* Bs = (__nv_bfloat16*)(smem + FM_RING + st*FM_RSTG);
        if (r < 8) {
            const __nv_bfloat16* Wg = W1t + (size_t)(nh2*128) * 256 + r*32;
#pragma unroll
            for (int i = 0; i < 2; i++) {
                int idx = tid + 256*i, row = idx >> 2, seg = idx & 3;
                cp_async16(Bs + row*B_STR + seg*8, Wg + (size_t)row*256 + seg*8);
            }
        } else {
            const __nv_bfloat16* Wg = W2t + nh2*128 + (r-8)*32;
#pragma unroll
            for (int i = 0; i < 4; i++) {
                int idx = tid + 256*i, row = idx >> 2, seg = idx & 3;
                cp_async16(Bs + row*B_STR + seg*8, Wg + (size_t)row*1024 + seg*8);
            }
        }
        cp_commit();
    };
    fill(0); fill(1); fill(2); fill(3);

    gsm[tid] = gate[b*256 + tid];

    // ---- gate + LN3 -> Ab bf16 ----
    {
        const float* Ag = y + (size_t)m0 * 256;
        const float* gp = gate + b*256;
        float gv[8], lg[8], lb[8];
#pragma unroll
        for (int j = 0; j < 8; j++) {
            int c = lane*8 + j;
            gv[j] = gp[c]; lg[j] = n3g[c]; lb[j] = n3b[c];
        }
#pragma unroll 1
        for (int i = 0; i < 16; i++) {
            int r = wid*16 + i;
            const float4* rp = (const float4*)(Ag + (size_t)r * 256 + lane*8);
            float4 va = rp[0], vb = rp[1];
            float v[8] = {va.x, va.y, va.z, va.w, vb.x, vb.y, vb.z, vb.w};
            float s = 0.f, s2 = 0.f;
#pragma unroll
            for (int j = 0; j < 8; j++) {
                v[j] *= gv[j]; s += v[j]; s2 += v[j]*v[j];
            }
#pragma unroll
            for (int o = 16; o; o >>= 1) {
                s  += __shfl_xor_sync(0xffffffffu, s,  o);
                s2 += __shfl_xor_sync(0xffffffffu, s2, o);
            }
            float mean = s * (1.f/256.f);
            float var  = s2 * (1.f/256.f) - mean*mean;
            float inv  = rsqrtf(var + 1e-5f);
#pragma unroll
            for (int k = 0; k < 4; k++) {
                float n0 = (v[2*k  ]-mean)*inv*lg[2*k  ] + lb[2*k  ];
                float n1 = (v[2*k+1]-mean)*inv*lg[2*k+1] + lb[2*k+1];
                *(u32*)&Ab[r*AB_STR + lane*8 + 2*k] = packbf(n0, n1);
            }
        }
    }

    float O[2][16][4];
#pragma unroll
    for (int i = 0; i < 2; i++)
#pragma unroll
        for (int j = 0; j < 16; j++)
#pragma unroll
            for (int q = 0; q < 4; q++) O[i][j][q] = 0.f;

    int ci = 0;
#pragma unroll 1
    for (int nh = 0; nh < 8; nh++) {
        // ---- GEMM1: H = Ab @ W1t[nh] (128x128x256) ----
        float acc1[2][8][4];
#pragma unroll
        for (int i = 0; i < 2; i++)
#pragma unroll
            for (int j = 0; j < 8; j++)
#pragma unroll
                for (int q = 0; q < 4; q++) acc1[i][j][q] = 0.f;

#pragma unroll 1
        for (int c = 0; c < 8; c++, ci++) {
            cp_wait3();
            __syncthreads();
            const u32 rb = sbase + FM_RING + (u32)(ci % 5)*FM_RSTG;
#pragma unroll
            for (int ks = 0; ks < 2; ks++) {
                const int kb = c*32 + ks*16;
                u32 af[2][4], bf[8][2];
#pragma unroll
                for (int mt = 0; mt < 2; mt++) {
                    u32 aaddr = sbase + (u32)(((wm*32 + mt*16 + a_dr)*AB_STR + kb + a_dk) * 2);
                    ldsm4(af[mt][0], af[mt][1], af[mt][2], af[mt][3], aaddr);
                }
#pragma unroll
                for (int p = 0; p < 4; p++) {
                    u32 baddr = rb + (u32)(((wn*64 + p*16 + b_dc)*B_STR + ks*16 + b_dk) * 2);
                    ldsm4(bf[2*p][0], bf[2*p][1], bf[2*p+1][0], bf[2*p+1][1], baddr);
                }
#pragma unroll
                for (int mt = 0; mt < 2; mt++)
#pragma unroll
                    for (int nt = 0; nt < 8; nt++)
                        mma_bf16(acc1[mt][nt], af[mt], bf[nt]);
            }
            if (ci + 4 < 96) fill(ci + 4); else cp_commit();
        }

        // ---- gelu -> Hs bf16 ----
#pragma unroll
        for (int nt = 0; nt < 8; nt++) {
            int colH = wn*64 + nt*8 + 2*tig;
            float bb0 = b1[nh*128 + colH], bb1 = b1[nh*128 + colH + 1];
#pragma unroll
            for (int mt = 0; mt < 2; mt++) {
                int r0 = wm*32 + mt*16 + g, r1 = r0 + 8;
                float v00 = gelu_exact(acc1[mt][nt][0] + bb0);
                float v01 = gelu_exact(acc1[mt][nt][1] + bb1);
                float v10 = gelu_exact(acc1[mt][nt][2] + bb0);
                float v11 = gelu_exact(acc1[mt][nt][3] + bb1);
                *(u32*)&Hs[r0*FM_HS_STR + colH] = packbf(v00, v01);
                *(u32*)&Hs[r1*FM_HS_STR + colH] = packbf(v10, v11);
            }
        }
        __syncthreads();

        // ---- GEMM2: O += gelu(H) @ W2t[:, nh] (128x256x128) ----
#pragma unroll 1
        for (int c2 = 0; c2 < 4; c2++, ci++) {
            cp_wait3();
            __syncthreads();
            const u32 rb = sbase + FM_RING + (u32)(ci % 5)*FM_RSTG;
#pragma unroll
            for (int ks = 0; ks < 2; ks++) {
                const int kh = c2*32 + ks*16;
                u32 af[2][4];
#pragma unroll
                for (int mt = 0; mt < 2; mt++) {
                    u32 aaddr = sbase + FM_HS +
                        (u32)(((wm*32 + mt*16 + a_dr)*FM_HS_STR + kh + a_dk) * 2);
                    ldsm4(af[mt][0], af[mt][1], af[mt][2], af[mt][3], aaddr);
                }
#pragma unroll
                for (int p = 0; p < 8; p++) {
                    u32 bf0, bf1, bf2, bf3;
                    u32 baddr = rb + (u32)(((wn*128 + p*16 + b_dc)*B_STR + ks*16 + b_dk) * 2);
                    ldsm4(bf0, bf1, bf2, bf3, baddr);
                    u32 bl[2][2] = {{bf0, bf1}, {bf2, bf3}};
#pragma unroll
                    for (int mt = 0; mt < 2; mt++) {
                        mma_bf16(O[mt][2*p],   af[mt], bl[0]);
                        mma_bf16(O[mt][2*p+1], af[mt], bl[1]);
                    }
                }
            }
            __syncthreads();
            if (ci + 4 < 96) fill(ci + 4); else cp_commit();
        }
    }

    // ---- final epilogue: out = O + b2 + y*gate (token-major fp32) ----
#pragma unroll
    for (int nt = 0; nt < 16; nt++) {
        int colG = wn*128 + nt*8 + 2*tig;
        float bb0 = b2[colG], bb1 = b2[colG + 1];
        float g0 = gsm[colG], g1 = gsm[colG + 1];
#pragma unroll
        for (int mt = 0; mt < 2; mt++) {
            size_t gr0 = (size_t)m0 + wm*32 + mt*16 + g;
            size_t gr1 = gr0 + 8;
            float2 q0 = *(const float2*)(y + gr0*256 + colG);
            float2 q1 = *(const float2*)(y + gr1*256 + colG);
            float v00 = O[mt][nt][0] + bb0 + q0.x*g0;
            float v01 = O[mt][nt][1] + bb1 + q0.y*g1;
            float v10 = O[mt][nt][2] + bb0 + q1.x*g0;
            float v11 = O[mt][nt][3] + bb1 + q1.y*g1;
            *(float2*)(outT + gr0*256 + colG) = make_float2(v00, v01);
            *(float2*)(outT + gr1*256 + colG) = make_float2(v10, v11);
        }
    }
}

// -------------------- SE gate from completed pooled sums --------------------
__global__ void __launch_bounds__(256) k_pool_gate(const float* __restrict__ part,
                                                   const float* __restrict__ w1,
                                                   const float* __restrict__ b1,
                                                   const float* __restrict__ w2,
                                                   const float* __restrict__ b2,
                                                   float* __restrict__ gate) {
    int b = blockIdx.x;
    float pooled = part[b*256 + threadIdx.x] * (1.f / (float)TOK_PER_B);
    __shared__ float sp[256];
    __shared__ float hid[16];
    sp[threadIdx.x] = pooled;
    __syncthreads();
    if (threadIdx.x < 16) {
        float a = b1[threadIdx.x];
        for (int c = 0; c < 256; c++) a = fmaf(sp[c], w1[c*16 + threadIdx.x], a);
        hid[threadIdx.x] = fmaxf(a, 0.f);
    }
    __syncthreads();
    float g = b2[threadIdx.x];
#pragma unroll
    for (int j = 0; j < 16; j++) g = fmaf(hid[j], w2[j*256 + threadIdx.x], g);
    gate[b*256 + threadIdx.x] = 1.f / (1.f + __expf(-g));
}

// ---------------------------------------------------------------------------
extern "C" void kernel_launch(void* const* d_in, const int* in_sizes, int n_in,
                              void* d_out, int out_size) {
    const float* x      = (const float*)d_in[0];
    const float* n1_g   = (const float*)d_in[1];
    const float* n1_b   = (const float*)d_in[2];
    const float* qkv_w  = (const float*)d_in[3];
    const float* qkv_b  = (const float*)d_in[4];
    const float* proj_w = (const float*)d_in[5];
    const float* proj_b = (const float*)d_in[6];
    const float* rel_b  = (const float*)d_in[7];
    const float* se_w1  = (const float*)d_in[8];
    const float* se_b1  = (const float*)d_in[9];
    const float* se_w2  = (const float*)d_in[10];
    const float* se_b2  = (const float*)d_in[11];
    const float* n3_g   = (const float*)d_in[12];
    const float* n3_b   = (const float*)d_in[13];
    const float* mlp_w1 = (const float*)d_in[14];
    const float* mlp_b1 = (const float*)d_in[15];
    const float* mlp_w2 = (const float*)d_in[16];
    const float* mlp_b2 = (const float*)d_in[17];
    float* out = (float*)d_out;

    float *wins, *hbuf, *part, *gate, *wb;
    cudaGetSymbolAddress((void**)&wins, g_wins);
    cudaGetSymbolAddress((void**)&hbuf, g_h);
    cudaGetSymbolAddress((void**)&part, g_part);
    cudaGetSymbolAddress((void**)&gate, g_gate);
    cudaGetSymbolAddress((void**)&wb,   g_wb);

    __nv_bfloat16* wbf   = (__nv_bfloat16*)wb;
    __nv_bfloat16* qkvW  = wbf;            // packed [8][96][256]
    __nv_bfloat16* projW = wbf + 196608;   // [256,256]
    __nv_bfloat16* w1W   = wbf + 262144;   // [1024,256]
    __nv_bfloat16* w2W   = wbf + 524288;   // [256,1024]
    __nv_bfloat16* hb    = (__nv_bfloat16*)hbuf;

    cudaFuncSetAttribute(k_fused_qkv_attn, cudaFuncAttributeMaxDynamicSharedMemorySize, FS_SMEM);
    cudaFuncSetAttribute(k_gemm_smA,  cudaFuncAttributeMaxDynamicSharedMemorySize, SMA_SMEM);
    cudaFuncSetAttribute(k_fused_mlp, cudaFuncAttributeMaxDynamicSharedMemorySize, FM_SMEM);

    dim3 b328(32, 8);
    dim3 gtr(WW_/32, HH, BATCH*8);

    k_winpart<<<gtr, b328>>>(x, wins, part);                              // 1
    k_wprep4<<<768, b328>>>(qkv_w, qkvW, mlp_w1, w1W,                     // 2
                            proj_w, projW, mlp_w2, w2W);
    k_fused_qkv_attn<<<NTOK/128, 256, FS_SMEM>>>(wins, n1_g, n1_b,        // 3
                                                 qkvW, qkv_b, rel_b, hb);
    k_gemm_smA<<<NTOK/256, 256, SMA_SMEM>>>(hb, projW, proj_b,            // 4 <- profiled
                                            wins, wins, 256, part);
    k_pool_gate<<<BATCH, 256>>>(part, se_w1, se_b1, se_w2, se_b2, gate);  // 5
    k_fused_mlp<<<NTOK/128, 256, FM_SMEM>>>(wins, gate, n3_g, n3_b,       // 6
                                            w1W, mlp_b1, w2W, mlp_b2, hbuf);
    k_winrev<<<gtr, b328>>>(hbuf, out);                                   // 7
}